// round 12
// baseline (speedup 1.0000x reference)
#include <cuda_runtime.h>
#include <cuda_bf16.h>
#include <cstdint>

// Problem constants
#define BDIM 16384
#define OBSD 512
#define HD   1024
#define NAG  9
#define NTOTH 2048          // fused head GEMM N (coop 1024 | cov 512 | trk 512)
#define NTILES 16           // part slices (fallback uses 16; tc uses first 8)

// ---- tcgen05 cg2 path: 256x512 tile per CTA pair, K=64 stages, 4-slot ring ----
#define TC_A_STAGE 16384                    // 128 rows x 128B
#define TC_B_STAGE 32768                    // 256 rows x 128B
#define SM_TMEM    0
#define SM_FULL    16
#define SM_DONE    24
#define SM_A       1024
#define SM_B       (SM_A + 4 * TC_A_STAGE)          // 66560
#define TC_SMEM    (SM_B + 4 * TC_B_STAGE)          // 197632

#if defined(__CUDA_ARCH_FEAT_SM103_ALL)
#define GEMM_BOUNDS __launch_bounds__(256, 1)
#else
#define GEMM_BOUNDS __launch_bounds__(256, 2)
#endif

// ---------------------------------------------------------------------------
// Static scratch (no allocation allowed)
// ---------------------------------------------------------------------------
__device__ __align__(16) __nv_bfloat16 g_obs [BDIM * OBSD];
__device__ __align__(16) __nv_bfloat16 g_W1t [HD * OBSD];      // [1024][512]
__device__ __align__(16) __nv_bfloat16 g_W2t [HD * HD];        // [1024][1024]
__device__ __align__(16) __nv_bfloat16 g_Wall[NTOTH * HD];     // [coop|cov|trk][1024]
__device__ __align__(16) float         g_ball[NTOTH];          // combined bias
__device__ __align__(16) float         g_w2v [NTOTH];          // combined layer-2 weights
__device__ __align__(16) __nv_bfloat16 g_g1  [BDIM * HD];
__device__ __align__(16) __nv_bfloat16 g_g2  [BDIM * HD];
__device__ __align__(16) float         g_part[NTILES * BDIM];  // partial logits

// ---------------------------------------------------------------------------
// Common PTX helpers
// ---------------------------------------------------------------------------
__device__ __forceinline__ void cpa16p(void* smem, const void* gmem) {
    uint32_t s = (uint32_t)__cvta_generic_to_shared(smem);
    asm volatile("cp.async.cg.shared.global [%0], [%1], 16;\n" :: "r"(s), "l"(gmem));
}
__device__ __forceinline__ void cpa16a(uint32_t s, const void* gmem) {
    asm volatile("cp.async.cg.shared.global [%0], [%1], 16;\n" :: "r"(s), "l"(gmem));
}
__device__ __forceinline__ void cpa_commit() {
    asm volatile("cp.async.commit_group;\n" ::: "memory");
}
__device__ __forceinline__ void cpa_wait0() {
    asm volatile("cp.async.wait_group 0;\n" ::: "memory");
}
__device__ __forceinline__ void cpa_wait2() {
    asm volatile("cp.async.wait_group 2;\n" ::: "memory");
}

// legacy HMMA (fallback pass)
__device__ __forceinline__ void mma_bf16(float* c, const uint32_t* a,
                                         uint32_t b0, uint32_t b1) {
    asm volatile(
        "mma.sync.aligned.m16n8k16.row.col.f32.bf16.bf16.f32 "
        "{%0,%1,%2,%3}, {%4,%5,%6,%7}, {%8,%9}, {%0,%1,%2,%3};\n"
        : "+f"(c[0]), "+f"(c[1]), "+f"(c[2]), "+f"(c[3])
        : "r"(a[0]), "r"(a[1]), "r"(a[2]), "r"(a[3]), "r"(b0), "r"(b1));
}

#if defined(__CUDA_ARCH_FEAT_SM103_ALL)
// ---------------- tcgen05-only helpers ('a' pass only) ---------------------
__device__ __forceinline__ void mbar_init(uint32_t m, uint32_t cnt) {
    asm volatile("mbarrier.init.shared.b64 [%0], %1;" :: "r"(m), "r"(cnt) : "memory");
}
__device__ __forceinline__ void mbar_inval(uint32_t m) {
    asm volatile("mbarrier.inval.shared.b64 [%0];" :: "r"(m) : "memory");
}
__device__ __forceinline__ void mbar_wait(uint32_t m, uint32_t parity) {
    asm volatile(
        "{\n\t.reg .pred P;\n"
        "W%=:\n\t"
        "mbarrier.try_wait.parity.acquire.cta.shared::cta.b64 P, [%0], %1, 0x989680;\n\t"
        "@P bra.uni D%=;\n\t"
        "bra.uni W%=;\n"
        "D%=:\n\t}"
        :: "r"(m), "r"(parity) : "memory");
}
__device__ __forceinline__ void mbar_wait_cluster(uint32_t m, uint32_t parity) {
    asm volatile(
        "{\n\t.reg .pred P;\n"
        "W%=:\n\t"
        "mbarrier.try_wait.parity.acquire.cluster.shared::cta.b64 P, [%0], %1, 0x989680;\n\t"
        "@P bra.uni D%=;\n\t"
        "bra.uni W%=;\n"
        "D%=:\n\t}"
        :: "r"(m), "r"(parity) : "memory");
}
// cg2 kind::f16 SS MMA (bf16 in, f32 acc in TMEM, M=256 across pair)
__device__ __forceinline__ void mma_f16_ss_cg2(uint32_t d_tmem, uint64_t a_desc,
                                               uint64_t b_desc, uint32_t idesc,
                                               bool accum) {
    uint32_t en = accum ? 1u : 0u;
    asm volatile(
        "{\n\t.reg .pred p;\n\t"
        "setp.ne.u32 p, %5, 0;\n\t"
        "tcgen05.mma.cta_group::2.kind::f16 [%0], %1, %2, %3, "
        "{%4, %4, %4, %4, %4, %4, %4, %4}, p;\n\t"
        "}"
        :: "r"(d_tmem), "l"(a_desc), "l"(b_desc), "r"(idesc), "r"(0u), "r"(en)
        : "memory");
}
__device__ __forceinline__ void tmem_ld32(uint32_t* r, uint32_t addr) {
    asm volatile(
        "tcgen05.ld.sync.aligned.32x32b.x32.b32 "
        "{%0, %1, %2, %3, %4, %5, %6, %7, "
        " %8, %9, %10, %11, %12, %13, %14, %15, "
        " %16, %17, %18, %19, %20, %21, %22, %23, "
        " %24, %25, %26, %27, %28, %29, %30, %31}, [%32];"
        : "=r"(r[0]),  "=r"(r[1]),  "=r"(r[2]),  "=r"(r[3]),
          "=r"(r[4]),  "=r"(r[5]),  "=r"(r[6]),  "=r"(r[7]),
          "=r"(r[8]),  "=r"(r[9]),  "=r"(r[10]), "=r"(r[11]),
          "=r"(r[12]), "=r"(r[13]), "=r"(r[14]), "=r"(r[15]),
          "=r"(r[16]), "=r"(r[17]), "=r"(r[18]), "=r"(r[19]),
          "=r"(r[20]), "=r"(r[21]), "=r"(r[22]), "=r"(r[23]),
          "=r"(r[24]), "=r"(r[25]), "=r"(r[26]), "=r"(r[27]),
          "=r"(r[28]), "=r"(r[29]), "=r"(r[30]), "=r"(r[31])
        : "r"(addr));
}
// SW128 K-major descriptor (layout=SW128, version=1, SBO=64, LBO=1)
__device__ __forceinline__ uint64_t make_desc(uint32_t smem_addr) {
    const uint64_t base =
        (uint64_t(2) << 61) | (uint64_t(1) << 46) | (uint64_t(64) << 32) | (uint64_t(1) << 16);
    return base | ((uint64_t)(smem_addr >> 4) & 0x3FFF);
}
#endif  // __CUDA_ARCH_FEAT_SM103_ALL

// ---------------------------------------------------------------------------
// Prep kernels
// ---------------------------------------------------------------------------
__global__ void k_cvt_bf16_v4(const float4* __restrict__ src,
                              __nv_bfloat16* __restrict__ dst, int n4) {
    int i = blockIdx.x * blockDim.x + threadIdx.x;
    int stride = gridDim.x * blockDim.x;
    for (; i < n4; i += stride) {
        float4 v = src[i];
        __nv_bfloat162 p0 = __floats2bfloat162_rn(v.x, v.y);
        __nv_bfloat162 p1 = __floats2bfloat162_rn(v.z, v.w);
        uint2 o;
        o.x = *(uint32_t*)&p0;
        o.y = *(uint32_t*)&p1;
        *(uint2*)&dst[(size_t)i * 4] = o;
    }
}

// All 5 weight transposes in one launch (blockIdx.z selects).
// dst[n*K + k] = bf16(src[k*N + n] (+ src2[k*N + n]))
__global__ void k_prep_weights(const float* __restrict__ W1,
                               const float* __restrict__ W2,
                               const float* __restrict__ Wc1,
                               const float* __restrict__ Wt1,
                               const float* __restrict__ Wk1) {
    const float* src = nullptr; const float* src2 = nullptr;
    __nv_bfloat16* dst = nullptr; int K = 0, N = 0;
    switch (blockIdx.z) {
        case 0: src = W1;  dst = g_W1t;                K = OBSD; N = HD;    break;
        case 1: src = W2;  dst = g_W2t;                K = HD;   N = HD;    break;
        case 2: src = Wc1; dst = g_Wall + 1024 * HD;   K = HD;   N = HD/2;  break;
        case 3: src = Wt1; dst = g_Wall + 1536 * HD;   K = HD;   N = HD/2;  break;
        case 4: src = Wk1; src2 = Wk1 + (size_t)HD*HD; dst = g_Wall; K = HD; N = HD; break;
    }
    int n0 = blockIdx.x * 32, k0 = blockIdx.y * 32;
    if (n0 >= N || k0 >= K) return;

    __shared__ float tile[32][33];
    int tx = threadIdx.x, ty = threadIdx.y;  // 32 x 8
    #pragma unroll
    for (int i = ty; i < 32; i += 8) {
        float v = src[(size_t)(k0 + i) * N + n0 + tx];
        if (src2) v += src2[(size_t)(k0 + i) * N + n0 + tx];
        tile[i][tx] = v;
    }
    __syncthreads();
    #pragma unroll
    for (int i = ty; i < 32; i += 8)
        dst[(size_t)(n0 + i) * K + k0 + tx] = __float2bfloat16(tile[tx][i]);
}

// Combined bias / layer-2 weight vectors + zero partial buffer.
__global__ void k_head_vecs_zero(const float* __restrict__ bk1, const float* __restrict__ Wk2,
                                 const float* __restrict__ bc1, const float* __restrict__ Wc2,
                                 const float* __restrict__ bt1, const float* __restrict__ Wt2) {
    int i = blockIdx.x * blockDim.x + threadIdx.x;
    if (i < NTOTH) {
        float b, w;
        if (i < 1024)      { b = bk1[i];        w = Wk2[i]; }
        else if (i < 1536) { b = bc1[i - 1024]; w = Wc2[i - 1024]; }
        else               { b = bt1[i - 1536]; w = Wt2[i - 1536]; }
        g_ball[i] = b; g_w2v[i] = w;
    }
    if (i < NTILES * BDIM) g_part[i] = 0.f;
}

// ---------------------------------------------------------------------------
// Unified GEMM: C[M,N] = relu(A[M,K] @ Bt[N,K]^T + bias)        (FUSED=false)
//            or part slices = relu(...)[r,:] . w2[:]             (FUSED=true)
// sm_103a pass: cta_group::2, 256x512 tile per CTA pair, cluster (2,1,1).
//   grid: x = Ntiles*2 (bit0 = cluster rank), y = M/256.
// sm_103 pass: mma.sync 128x128 fallback. grid: x = N/128, y = M/128.
// ---------------------------------------------------------------------------
template<bool FUSED>
__global__ void GEMM_BOUNDS __cluster_dims__(2, 1, 1)
k_gemm(const __nv_bfloat16* __restrict__ A,
       const __nv_bfloat16* __restrict__ Bt,
       const float* __restrict__ bias,
       const float* __restrict__ w2,
       __nv_bfloat16* __restrict__ C,
       float* __restrict__ part,
       int K, int Ntot) {
    const int tid = threadIdx.x, wid = tid >> 5, lane = tid & 31;

#if defined(__CUDA_ARCH_FEAT_SM103_ALL)
    // =================== tcgen05 cg2 path ===================
    extern __shared__ __align__(1024) char smem[];
    const uint32_t sb = (uint32_t)__cvta_generic_to_shared(smem);
    const int rank  = blockIdx.x & 1;
    const int n0    = (blockIdx.x >> 1) * 512;
    const int m0cta = blockIdx.y * 256 + rank * 128;   // this CTA's 128 A-rows

    if (wid == 0) {
        asm volatile("tcgen05.alloc.cta_group::2.sync.aligned.shared::cta.b32 [%0], %1;"
                     :: "r"(sb + SM_TMEM), "r"(512) : "memory");
        asm volatile("tcgen05.relinquish_alloc_permit.cta_group::2.sync.aligned;");
    }
    if (tid == 0) {
        mbar_init(sb + SM_FULL, 2);   // both CTAs arrive per stage
        mbar_init(sb + SM_DONE, 1);   // MMA commit (multicast) arrives
    }
    __syncthreads();
    // cluster barrier: peer mbarriers must be init'd before cross-CTA arrivals
    asm volatile("barrier.cluster.arrive.aligned;" ::: "memory");
    asm volatile("barrier.cluster.wait.aligned;" ::: "memory");

    uint32_t tmem;
    asm volatile("ld.shared.b32 %0, [%1];" : "=r"(tmem) : "r"(sb + SM_TMEM));

    const __nv_bfloat16* gA = A + (size_t)m0cta * K;
    // B rows this CTA holds: dispatch j half = global rows n0 + j*256 + rank*128 + [0,128)
    const __nv_bfloat16* gB = Bt + (size_t)(n0 + rank * 128) * K;

    auto load_stage = [&](int s) {
        const uint32_t ab = sb + SM_A + (s & 3) * TC_A_STAGE;
        const uint32_t bb = sb + SM_B + (s & 3) * TC_B_STAGE;
        const int k0 = s * 64;
        #pragma unroll
        for (int i = 0; i < 4; i++) {            // A: 128 rows x 8 chunks
            int c = tid + i * 256;
            int row = c >> 3, col = c & 7;
            uint32_t off = row * 128 + col * 16;
            off ^= (off >> 3) & 0x70;
            cpa16a(ab + off, gA + (size_t)row * K + k0 + col * 8);
        }
        #pragma unroll
        for (int i = 0; i < 8; i++) {            // B: 256 rows x 8 chunks
            int c = tid + i * 256;
            int row = c >> 3, col = c & 7;       // row 0..255
            uint32_t off = row * 128 + col * 16;
            off ^= (off >> 3) & 0x70;
            const __nv_bfloat16* src =
                gB + ((size_t)(row & 127) + (size_t)(row >> 7) * 256) * K + k0 + col * 8;
            cpa16a(bb + off, src);
        }
    };

    const int T = K / 64;
    #pragma unroll
    for (int s = 0; s < 3; s++) { load_stage(s); cpa_commit(); }

    // idesc: f32 acc | bf16 A | bf16 B | N=256 | M=256
    const uint32_t IDESC = (1u << 4) | (1u << 7) | (1u << 10) | (32u << 17) | (16u << 24);
    const uint64_t ad0 = make_desc(sb + SM_A);
    const uint64_t bd0 = make_desc(sb + SM_B);

    uint32_t full_rem;   // leader CTA's full-mbar address
    asm("mapa.shared::cluster.u32 %0, %1, 0;" : "=r"(full_rem) : "r"(sb + SM_FULL));

    for (int t = 0; t < T; t++) {
        cpa_wait2();                 // this CTA's stage t data in smem
        __syncthreads();
        asm volatile("fence.proxy.async.shared::cta;" ::: "memory");
        if (tid == 0)                // signal leader: my stage-t tiles ready
            asm volatile("mbarrier.arrive.release.cluster.shared::cluster.b64 _, [%0];"
                         :: "r"(full_rem) : "memory");
        if (t > 0) mbar_wait(sb + SM_DONE, (t - 1) & 1);   // MMA(t-1) done
        if (rank == 0 && tid == 0) {
            mbar_wait_cluster(sb + SM_FULL, t & 1);        // both CTAs ready
            uint64_t ad = ad0 + (uint64_t)(t & 3) * (TC_A_STAGE >> 4);
            uint64_t bd = bd0 + (uint64_t)(t & 3) * (TC_B_STAGE >> 4);
            #pragma unroll
            for (int j = 0; j < 2; j++)          // two N=256 halves
                #pragma unroll
                for (int kk = 0; kk < 4; kk++)   // 4 x K=16 per stage
                    mma_f16_ss_cg2(tmem + j * 256, ad + kk * 2,
                                   bd + (uint64_t)j * 1024 + kk * 2, IDESC,
                                   (t > 0) || (kk > 0));
            asm volatile(
                "tcgen05.commit.cta_group::2.mbarrier::arrive::one."
                "shared::cluster.multicast::cluster.b64 [%0], %1;"
                :: "r"(sb + SM_DONE), "h"((uint16_t)3) : "memory");
        }
        if (t + 3 < T) load_stage(t + 3);        // overwrites slot (t-1)&3
        cpa_commit();
    }
    mbar_wait(sb + SM_DONE, (T - 1) & 1);
    asm volatile("tcgen05.fence::after_thread_sync;" ::: "memory");

    // Epilogue: each CTA owns 128 rows x 512 cols of D.
    // Warps (wid&3) pick the row group; (wid>>2) picks the 256-col half.
    const int r  = m0cta + (wid & 3) * 32 + lane;
    const int cb = (wid >> 2) * 256;
    if (!FUSED) {
        #pragma unroll
        for (int ch = 0; ch < 8; ch++) {
            uint32_t d[32];
            tmem_ld32(d, tmem + cb + ch * 32);
            asm volatile("tcgen05.wait::ld.sync.aligned;" ::: "memory");
            const int col0 = n0 + cb + ch * 32;
            #pragma unroll
            for (int q = 0; q < 4; q++) {
                uint4 v;
                #pragma unroll
                for (int e = 0; e < 4; e++) {
                    int c = q * 8 + e * 2;
                    float x0 = fmaxf(__uint_as_float(d[c])     + bias[col0 + c],     0.f);
                    float x1 = fmaxf(__uint_as_float(d[c + 1]) + bias[col0 + c + 1], 0.f);
                    __nv_bfloat162 p = __floats2bfloat162_rn(x0, x1);
                    ((uint32_t*)&v)[e] = *(uint32_t*)&p;
                }
                *(uint4*)&C[(size_t)r * Ntot + col0 + q * 8] = v;
            }
        }
    } else {
        float ps = 0.f;
        #pragma unroll
        for (int ch = 0; ch < 8; ch++) {
            uint32_t d[32];
            tmem_ld32(d, tmem + cb + ch * 32);
            asm volatile("tcgen05.wait::ld.sync.aligned;" ::: "memory");
            const int col0 = n0 + cb + ch * 32;
            #pragma unroll
            for (int c = 0; c < 32; c++) {
                float x = fmaxf(__uint_as_float(d[c]) + bias[col0 + c], 0.f);
                ps += x * w2[col0 + c];
            }
        }
        // slice = ntile*2 + column-half; one thread owns each (slice,row): plain store
        const int slice = (blockIdx.x >> 1) * 2 + (wid >> 2);
        part[(size_t)slice * BDIM + r] = ps;
    }

    asm volatile("tcgen05.fence::before_thread_sync;" ::: "memory");
    __syncthreads();
    if (tid == 0) { mbar_inval(sb + SM_FULL); mbar_inval(sb + SM_DONE); }
    __syncthreads();
    if (wid == 0)
        asm volatile("tcgen05.dealloc.cta_group::2.sync.aligned.b32 %0, %1;"
                     :: "r"(tmem), "r"(512));
    asm volatile("barrier.cluster.arrive.aligned;" ::: "memory");
    asm volatile("barrier.cluster.wait.aligned;" ::: "memory");

#else
    // =================== mma.sync fallback (128x128, BK=64) =================
    const int n0 = blockIdx.x * 128, m0 = blockIdx.y * 128;
    #define BKP 72
    __shared__ __nv_bfloat16 As[2][128 * BKP];
    __shared__ __nv_bfloat16 Bs[2][128 * BKP];

    const int g  = lane >> 2;
    const int tg = lane & 3;
    const int warp_m = (wid & 3) * 32;
    const int warp_n = (wid >> 2) * 64;

    float acc[2][8][4];
    #pragma unroll
    for (int a = 0; a < 2; a++)
        #pragma unroll
        for (int b = 0; b < 8; b++)
            #pragma unroll
            for (int c = 0; c < 4; c++) acc[a][b][c] = 0.f;

    const int KT = K / 64;

    auto load_tile = [&](int kt, int buf) {
        const int k0 = kt * 64;
        #pragma unroll
        for (int i = 0; i < 4; i++) {
            int c   = tid + i * 256;
            int row = c >> 3;
            int cc  = (c & 7) * 8;
            cpa16p(&As[buf][row * BKP + cc], A + (size_t)(m0 + row) * K + k0 + cc);
            cpa16p(&Bs[buf][row * BKP + cc], Bt + (size_t)(n0 + row) * K + k0 + cc);
        }
        cpa_commit();
    };

    load_tile(0, 0);

    for (int kt = 0; kt < KT; kt++) {
        const int buf = kt & 1;
        cpa_wait0();
        __syncthreads();
        if (kt + 1 < KT) load_tile(kt + 1, buf ^ 1);

        #pragma unroll
        for (int ks = 0; ks < 4; ks++) {
            const int kk = ks * 16;
            uint32_t afr[2][4];
            #pragma unroll
            for (int mi = 0; mi < 2; mi++) {
                const int rr = warp_m + mi * 16 + g;
                const __nv_bfloat16* base = &As[buf][0];
                afr[mi][0] = *(const uint32_t*)(base + (rr)     * BKP + kk +     2 * tg);
                afr[mi][1] = *(const uint32_t*)(base + (rr + 8) * BKP + kk +     2 * tg);
                afr[mi][2] = *(const uint32_t*)(base + (rr)     * BKP + kk + 8 + 2 * tg);
                afr[mi][3] = *(const uint32_t*)(base + (rr + 8) * BKP + kk + 8 + 2 * tg);
            }
            #pragma unroll
            for (int ni = 0; ni < 8; ni++) {
                const int nn = warp_n + ni * 8 + g;
                const __nv_bfloat16* bbase = &Bs[buf][0];
                uint32_t b0 = *(const uint32_t*)(bbase + nn * BKP + kk +     2 * tg);
                uint32_t b1 = *(const uint32_t*)(bbase + nn * BKP + kk + 8 + 2 * tg);
                #pragma unroll
                for (int mi = 0; mi < 2; mi++)
                    mma_bf16(acc[mi][ni], afr[mi], b0, b1);
            }
        }
        __syncthreads();
    }

    if (!FUSED) {
        #pragma unroll
        for (int mi = 0; mi < 2; mi++) {
            const int rr = m0 + warp_m + mi * 16 + g;
            #pragma unroll
            for (int ni = 0; ni < 8; ni++) {
                const int col = n0 + warp_n + ni * 8 + 2 * tg;
                float bi0 = bias[col], bi1 = bias[col + 1];
                float v0 = fmaxf(acc[mi][ni][0] + bi0, 0.f);
                float v1 = fmaxf(acc[mi][ni][1] + bi1, 0.f);
                float v2 = fmaxf(acc[mi][ni][2] + bi0, 0.f);
                float v3 = fmaxf(acc[mi][ni][3] + bi1, 0.f);
                __nv_bfloat162 p0 = __floats2bfloat162_rn(v0, v1);
                __nv_bfloat162 p1 = __floats2bfloat162_rn(v2, v3);
                *(__nv_bfloat162*)&C[(size_t)rr * Ntot + col]       = p0;
                *(__nv_bfloat162*)&C[(size_t)(rr + 8) * Ntot + col] = p1;
            }
        }
    } else {
        #pragma unroll
        for (int mi = 0; mi < 2; mi++) {
            float s0 = 0.f, s1 = 0.f;
            #pragma unroll
            for (int ni = 0; ni < 8; ni++) {
                const int col = n0 + warp_n + ni * 8 + 2 * tg;
                float bi0 = bias[col], bi1 = bias[col + 1];
                float w0 = w2[col],   w1 = w2[col + 1];
                s0 += fmaxf(acc[mi][ni][0] + bi0, 0.f) * w0
                    + fmaxf(acc[mi][ni][1] + bi1, 0.f) * w1;
                s1 += fmaxf(acc[mi][ni][2] + bi0, 0.f) * w0
                    + fmaxf(acc[mi][ni][3] + bi1, 0.f) * w1;
            }
            #pragma unroll
            for (int o = 1; o <= 2; o <<= 1) {
                s0 += __shfl_xor_sync(0xFFFFFFFFu, s0, o);
                s1 += __shfl_xor_sync(0xFFFFFFFFu, s1, o);
            }
            if (tg == 0) {
                const int rr = m0 + warp_m + mi * 16 + g;
                atomicAdd(&part[(size_t)blockIdx.x * BDIM + rr],     s0);
                atomicAdd(&part[(size_t)blockIdx.x * BDIM + rr + 8], s1);
            }
        }
    }
    #undef BKP
#endif
}

// ---------------------------------------------------------------------------
// Finalize. tc layout: 8 slices (ntile*2 + half): 0-3 coop, 4-5 cov, 6-7 trk.
// fallback layout: 16 x 128-col tiles (0-7 coop, 8-11 cov, 12-15 trk).
// ---------------------------------------------------------------------------
__global__ void k_finalize(const float* __restrict__ part,
                           const float* __restrict__ bc2,
                           const float* __restrict__ bt2,
                           const float* __restrict__ bk2,
                           float* __restrict__ out, int tc) {
    int r = blockIdx.x * blockDim.x + threadIdx.x;
    if (r >= BDIM) return;
    float coop = 0.f, cov = 0.f, trk = 0.f;
    if (tc) {
        coop = part[r] + part[(size_t)BDIM + r]
             + part[(size_t)2 * BDIM + r] + part[(size_t)3 * BDIM + r];
        cov  = part[(size_t)4 * BDIM + r] + part[(size_t)5 * BDIM + r];
        trk  = part[(size_t)6 * BDIM + r] + part[(size_t)7 * BDIM + r];
    } else {
        #pragma unroll
        for (int t = 0; t < 8; t++)   coop += part[(size_t)t * BDIM + r];
        #pragma unroll
        for (int t = 8; t < 12; t++)  cov  += part[(size_t)t * BDIM + r];
        #pragma unroll
        for (int t = 12; t < 16; t++) trk  += part[(size_t)t * BDIM + r];
    }
    coop = 1.f / (1.f + expf(-(coop + bk2[0])));
    cov  = 1.f / (1.f + expf(-(cov  + bc2[0])));
    trk  = 1.f / (1.f + expf(-(trk  + bt2[0])));
    float* o0 = out + (size_t)r * NAG;
    float* o1 = out + (size_t)BDIM * NAG + (size_t)r * NAG;
    float* o2 = out + (size_t)2 * BDIM * NAG + (size_t)r * NAG;
    #pragma unroll
    for (int j = 0; j < NAG; j++) { o0[j] = cov; o1[j] = trk; o2[j] = coop; }
}

// ---------------------------------------------------------------------------
// Launch
// ---------------------------------------------------------------------------
extern "C" void kernel_launch(void* const* d_in, const int* in_sizes, int n_in,
                              void* d_out, int out_size) {
    (void)in_sizes; (void)n_in; (void)out_size;

    const float* obs = (const float*)d_in[0];
    const float* W1  = (const float*)d_in[2];
    const float* b1  = (const float*)d_in[3];
    const float* W2  = (const float*)d_in[4];
    const float* b2  = (const float*)d_in[5];
    const float* Wc1 = (const float*)d_in[6];
    const float* bc1 = (const float*)d_in[7];
    const float* Wc2 = (const float*)d_in[8];
    const float* bc2 = (const float*)d_in[9];
    const float* Wt1 = (const float*)d_in[10];
    const float* bt1 = (const float*)d_in[11];
    const float* Wt2 = (const float*)d_in[12];
    const float* bt2 = (const float*)d_in[13];
    const float* Wk1 = (const float*)d_in[14];
    const float* bk1 = (const float*)d_in[15];
    const float* Wk2 = (const float*)d_in[16];
    const float* bk2 = (const float*)d_in[17];
    float* out = (float*)d_out;

    void *p_obs, *p_W1t, *p_W2t, *p_Wall, *p_ball, *p_w2, *p_g1, *p_g2, *p_part;
    cudaGetSymbolAddress(&p_obs,  g_obs);
    cudaGetSymbolAddress(&p_W1t,  g_W1t);
    cudaGetSymbolAddress(&p_W2t,  g_W2t);
    cudaGetSymbolAddress(&p_Wall, g_Wall);
    cudaGetSymbolAddress(&p_ball, g_ball);
    cudaGetSymbolAddress(&p_w2,   g_w2v);
    cudaGetSymbolAddress(&p_g1,   g_g1);
    cudaGetSymbolAddress(&p_g2,   g_g2);
    cudaGetSymbolAddress(&p_part, g_part);

    // Which device body got compiled? fallback has ~73KB static smem.
    cudaFuncAttributes fa{};
    cudaFuncGetAttributes(&fa, k_gemm<false>);
    const bool tc = (fa.sharedSizeBytes < 8192);
    size_t dyn = 0;
    if (tc) {
        cudaFuncSetAttribute(k_gemm<false>,
                             cudaFuncAttributeMaxDynamicSharedMemorySize, TC_SMEM);
        cudaFuncSetAttribute(k_gemm<true>,
                             cudaFuncAttributeMaxDynamicSharedMemorySize, TC_SMEM);
        dyn = TC_SMEM;
    }

    // prep
    k_cvt_bf16_v4<<<2048, 256>>>((const float4*)obs, (__nv_bfloat16*)p_obs,
                                 BDIM * OBSD / 4);
    k_prep_weights<<<dim3(32, 32, 5), dim3(32, 8)>>>(W1, W2, Wc1, Wt1, Wk1);
    k_head_vecs_zero<<<(NTILES * BDIM + 255) / 256, 256>>>(bk1, Wk2, bc1, Wc2, bt1, Wt2);

    if (tc) {
        // cg2 grids: x = Ntiles*2 (cluster pairs), y = M/256
        k_gemm<false><<<dim3((HD / 512) * 2, BDIM / 256), 256, dyn>>>(
            (const __nv_bfloat16*)p_obs, (const __nv_bfloat16*)p_W1t, b1, nullptr,
            (__nv_bfloat16*)p_g1, nullptr, OBSD, HD);
        k_gemm<false><<<dim3((HD / 512) * 2, BDIM / 256), 256, dyn>>>(
            (const __nv_bfloat16*)p_g1, (const __nv_bfloat16*)p_W2t, b2, nullptr,
            (__nv_bfloat16*)p_g2, nullptr, HD, HD);
        k_gemm<true><<<dim3((NTOTH / 512) * 2, BDIM / 256), 256, dyn>>>(
            (const __nv_bfloat16*)p_g2, (const __nv_bfloat16*)p_Wall,
            (const float*)p_ball, (const float*)p_w2,
            nullptr, (float*)p_part, HD, NTOTH);
    } else {
        k_gemm<false><<<dim3(HD / 128, BDIM / 128), 256, dyn>>>(
            (const __nv_bfloat16*)p_obs, (const __nv_bfloat16*)p_W1t, b1, nullptr,
            (__nv_bfloat16*)p_g1, nullptr, OBSD, HD);
        k_gemm<false><<<dim3(HD / 128, BDIM / 128), 256, dyn>>>(
            (const __nv_bfloat16*)p_g1, (const __nv_bfloat16*)p_W2t, b2, nullptr,
            (__nv_bfloat16*)p_g2, nullptr, HD, HD);
        k_gemm<true><<<dim3(NTOTH / 128, BDIM / 128), 256, dyn>>>(
            (const __nv_bfloat16*)p_g2, (const __nv_bfloat16*)p_Wall,
            (const float*)p_ball, (const float*)p_w2,
            nullptr, (float*)p_part, HD, NTOTH);
    }

    // finalize
    k_finalize<<<(BDIM + 255) / 256, 256>>>((const float*)p_part, bc2, bt2, bk2,
                                            out, tc ? 1 : 0);
}